// round 14
// baseline (speedup 1.0000x reference)
#include <cuda_runtime.h>
#include <stdint.h>

#define D 128
#define MAX_N (1 << 18)

__device__ int   g_cnt[MAX_N];
__device__ float g_inv[MAX_N];

// ---------------------------------------------------------------------------
// K0: zero counts
// ---------------------------------------------------------------------------
__global__ void zero_cnt_kernel(int N) {
    int i = blockIdx.x * blockDim.x + threadIdx.x;
    if (i < N) g_cnt[i] = 0;
}

// ---------------------------------------------------------------------------
// K1: histogram of segment ids, 4 edges/thread (vectorized, streaming loads)
// ---------------------------------------------------------------------------
__global__ void hist_kernel(const int* __restrict__ index, long long E) {
    long long base = ((long long)blockIdx.x * blockDim.x + threadIdx.x) * 4;
    if (base >= E) return;
    if (base + 4 <= E) {
        int4 v = __ldcs((const int4*)(index + base));
        atomicAdd(&g_cnt[v.x], 1);
        atomicAdd(&g_cnt[v.y], 1);
        atomicAdd(&g_cnt[v.z], 1);
        atomicAdd(&g_cnt[v.w], 1);
    } else {
        for (long long e = base; e < E; e++)
            atomicAdd(&g_cnt[__ldg(&index[e])], 1);
    }
}

// ---------------------------------------------------------------------------
// K2: zero output + compute reciprocal counts
// ---------------------------------------------------------------------------
__global__ void prep_kernel(float4* __restrict__ out4, long long n4, int N) {
    long long i = (long long)blockIdx.x * blockDim.x + threadIdx.x;
    long long stride = (long long)gridDim.x * blockDim.x;
    for (long long k = i; k < n4; k += stride)
        out4[k] = make_float4(0.f, 0.f, 0.f, 0.f);
    for (long long k = i; k < N; k += stride) {
        int c = g_cnt[k];
        g_inv[k] = 1.0f / (float)max(c, 1);
    }
}

// ---------------------------------------------------------------------------
// K3: scatter-mean. 4 edges per warp; msg/index streamed (evict-first),
//     RED destination hinted evict-last so the 51 MB output working set
//     stays pinned in L2 while the 1 GB stream passes through.
//     Contributions pre-scaled by 1/count -> output is the final mean.
// ---------------------------------------------------------------------------
__global__ __launch_bounds__(256) void scatter_kernel(
        const float4* __restrict__ msg4,
        const int* __restrict__ index,
        float* __restrict__ out,
        long long E) {
    long long warp_id = ((long long)blockIdx.x * blockDim.x + threadIdx.x) >> 5;
    int lane = threadIdx.x & 31;
    long long base = warp_id * 4;
    if (base >= E) return;
    int nb = (int)min(4LL, E - base);

    uint64_t pol;
    asm("createpolicy.fractional.L2::evict_last.b64 %0, 1.0;" : "=l"(pol));

    // lanes 0..3: coalesced index load + reciprocal lookup
    int seg = 0;
    float inv = 0.f;
    if (lane < nb) {
        seg = __ldcs(&index[base + lane]);
        inv = g_inv[seg];
    }

    // front-batch the 4 independent row loads — streaming, evict-first
    float4 v[4];
#pragma unroll
    for (int e = 0; e < 4; e++)
        if (e < nb) v[e] = __ldcs(&msg4[(base + e) * (D / 4) + lane]);

#pragma unroll
    for (int e = 0; e < 4; e++) {
        if (e >= nb) break;
        int   segE = __shfl_sync(0xffffffffu, seg, e);
        float invE = __shfl_sync(0xffffffffu, inv, e);
        float4 w = v[e];
        w.x *= invE; w.y *= invE; w.z *= invE; w.w *= invE;
        float* dst = out + (long long)segE * D + lane * 4;
        asm volatile(
            "red.global.add.L2::cache_hint.v4.f32 [%0], {%1,%2,%3,%4}, %5;"
            :: "l"(dst), "f"(w.x), "f"(w.y), "f"(w.z), "f"(w.w), "l"(pol)
            : "memory");
    }
}

// ---------------------------------------------------------------------------
extern "C" void kernel_launch(void* const* d_in, const int* in_sizes, int n_in,
                              void* d_out, int out_size) {
    const float4* msg4  = (const float4*)d_in[0];
    const int*    index = (const int*)d_in[1];
    // d_in[2] (t) unused by the reference
    float* out = (float*)d_out;

    long long E = in_sizes[1];
    int N = out_size / D;
    long long n4 = (long long)out_size / 4;

    zero_cnt_kernel<<<(N + 255) / 256, 256>>>(N);
    hist_kernel<<<(int)((E + 1023) / 1024), 256>>>(index, E);
    prep_kernel<<<2048, 256>>>((float4*)out, n4, N);
    {
        long long warps = (E + 3) / 4;
        long long threads = warps * 32;
        int blocks = (int)((threads + 255) / 256);
        scatter_kernel<<<blocks, 256>>>(msg4, index, out, E);
    }
}

// round 15
// speedup vs baseline: 1.0011x; 1.0011x over previous
#include <cuda_runtime.h>
#include <stdint.h>

#define D 128
#define MAX_N (1 << 18)

__device__ int   g_cnt[MAX_N];
__device__ float g_inv[MAX_N];

// ---------------------------------------------------------------------------
// K0: zero counts
// ---------------------------------------------------------------------------
__global__ void zero_cnt_kernel(int N) {
    int i = blockIdx.x * blockDim.x + threadIdx.x;
    if (i < N) g_cnt[i] = 0;
}

// ---------------------------------------------------------------------------
// K1: histogram of segment ids, 4 edges/thread (vectorized, streaming loads)
// ---------------------------------------------------------------------------
__global__ void hist_kernel(const int* __restrict__ index, long long E) {
    long long base = ((long long)blockIdx.x * blockDim.x + threadIdx.x) * 4;
    if (base >= E) return;
    if (base + 4 <= E) {
        int4 v = __ldcs((const int4*)(index + base));
        atomicAdd(&g_cnt[v.x], 1);
        atomicAdd(&g_cnt[v.y], 1);
        atomicAdd(&g_cnt[v.z], 1);
        atomicAdd(&g_cnt[v.w], 1);
    } else {
        for (long long e = base; e < E; e++)
            atomicAdd(&g_cnt[__ldg(&index[e])], 1);
    }
}

// ---------------------------------------------------------------------------
// K2: zero output + compute reciprocal counts
// ---------------------------------------------------------------------------
__global__ void prep_kernel(float4* __restrict__ out4, long long n4, int N) {
    long long i = (long long)blockIdx.x * blockDim.x + threadIdx.x;
    long long stride = (long long)gridDim.x * blockDim.x;
    for (long long k = i; k < n4; k += stride)
        out4[k] = make_float4(0.f, 0.f, 0.f, 0.f);
    for (long long k = i; k < N; k += stride) {
        int c = g_cnt[k];
        g_inv[k] = 1.0f / (float)max(c, 1);
    }
}

// ---------------------------------------------------------------------------
// K3: scatter-mean. 4 edges per warp; msg/index streamed (evict-first),
//     RED destination hinted evict-last so the 51 MB output working set
//     stays pinned in L2 while the 1 GB stream passes through.
//     Contributions pre-scaled by 1/count -> output is the final mean.
// ---------------------------------------------------------------------------
__global__ __launch_bounds__(256) void scatter_kernel(
        const float4* __restrict__ msg4,
        const int* __restrict__ index,
        float* __restrict__ out,
        long long E) {
    long long warp_id = ((long long)blockIdx.x * blockDim.x + threadIdx.x) >> 5;
    int lane = threadIdx.x & 31;
    long long base = warp_id * 4;
    if (base >= E) return;
    int nb = (int)min(4LL, E - base);

    uint64_t pol;
    asm("createpolicy.fractional.L2::evict_last.b64 %0, 1.0;" : "=l"(pol));

    // lanes 0..3: coalesced index load + reciprocal lookup
    int seg = 0;
    float inv = 0.f;
    if (lane < nb) {
        seg = __ldcs(&index[base + lane]);
        inv = g_inv[seg];
    }

    // front-batch the 4 independent row loads — streaming, evict-first
    float4 v[4];
#pragma unroll
    for (int e = 0; e < 4; e++)
        if (e < nb) v[e] = __ldcs(&msg4[(base + e) * (D / 4) + lane]);

#pragma unroll
    for (int e = 0; e < 4; e++) {
        if (e >= nb) break;
        int   segE = __shfl_sync(0xffffffffu, seg, e);
        float invE = __shfl_sync(0xffffffffu, inv, e);
        float4 w = v[e];
        w.x *= invE; w.y *= invE; w.z *= invE; w.w *= invE;
        float* dst = out + (long long)segE * D + lane * 4;
        asm volatile(
            "red.global.add.L2::cache_hint.v4.f32 [%0], {%1,%2,%3,%4}, %5;"
            :: "l"(dst), "f"(w.x), "f"(w.y), "f"(w.z), "f"(w.w), "l"(pol)
            : "memory");
    }
}

// ---------------------------------------------------------------------------
extern "C" void kernel_launch(void* const* d_in, const int* in_sizes, int n_in,
                              void* d_out, int out_size) {
    const float4* msg4  = (const float4*)d_in[0];
    const int*    index = (const int*)d_in[1];
    // d_in[2] (t) unused by the reference
    float* out = (float*)d_out;

    long long E = in_sizes[1];
    int N = out_size / D;
    long long n4 = (long long)out_size / 4;

    zero_cnt_kernel<<<(N + 255) / 256, 256>>>(N);
    hist_kernel<<<(int)((E + 1023) / 1024), 256>>>(index, E);
    prep_kernel<<<2048, 256>>>((float4*)out, n4, N);
    {
        long long warps = (E + 3) / 4;
        long long threads = warps * 32;
        int blocks = (int)((threads + 255) / 256);
        scatter_kernel<<<blocks, 256>>>(msg4, index, out, E);
    }
}